// round 2
// baseline (speedup 1.0000x reference)
#include <cuda_runtime.h>
#include <cstdint>
#include <cstddef>

#define S_SRC 2048
#define S_TGT 2048
#define BATCH 16
#define HDIM  256

// Scratch (device globals: allocation-free rule)
__device__ float g_enc [(size_t)BATCH * S_SRC * HDIM];   // [b][s][h] fp32
__device__ float g_encT[(size_t)BATCH * HDIM  * S_SRC];  // [b][h][s] fp32
__device__ float g_dec [(size_t)BATCH * S_TGT * HDIM];   // [b][t][h] fp32
__device__ float g_S   [(size_t)BATCH * S_TGT * S_SRC];  // [b][t][s] scores -> probs

__device__ __forceinline__ float to_tf32(float x) {
    float r;
    asm("cvt.rna.tf32.f32 %0, %1;" : "=f"(r) : "f"(x));
    return r;
}

// ---------------------------------------------------------------------------
// Kernel 1: enc = dir0 + dir1, batch-major transposes (full fp32, no rounding)
// ---------------------------------------------------------------------------
__global__ void __launch_bounds__(256) prep_kernel(const float* __restrict__ out_e,
                                                   const float* __restrict__ out_d) {
    int i = blockIdx.x * blockDim.x + threadIdx.x;
    int h = i & (HDIM - 1);
    int s = (i >> 8) & (S_SRC - 1);
    int b = i >> 19;
    size_t ebase = ((size_t)s * BATCH + b) * (2 * HDIM);
    float e = out_e[ebase + h] + out_e[ebase + HDIM + h];
    g_enc[((size_t)b * S_SRC + s) * HDIM + h] = e;
    float d = out_d[((size_t)s * BATCH + b) * HDIM + h];
    g_dec[((size_t)b * S_TGT + s) * HDIM + h] = d;
}

// ---------------------------------------------------------------------------
// Kernel 2: encT[b][h][s] = enc[b][s][h]
// ---------------------------------------------------------------------------
__global__ void __launch_bounds__(256) transpose_kernel() {
    __shared__ float tile[32][33];
    int b  = blockIdx.z;
    int s0 = blockIdx.x * 32;
    int h0 = blockIdx.y * 32;
    const float* src = g_enc  + (size_t)b * S_SRC * HDIM;
    float*       dst = g_encT + (size_t)b * HDIM  * S_SRC;
    int x = threadIdx.x;
    #pragma unroll
    for (int y = threadIdx.y; y < 32; y += 8)
        tile[y][x] = src[(size_t)(s0 + y) * HDIM + h0 + x];
    __syncthreads();
    #pragma unroll
    for (int y = threadIdx.y; y < 32; y += 8)
        dst[(size_t)(h0 + y) * S_SRC + s0 + x] = tile[x][y];
}

// ---------------------------------------------------------------------------
// tf32 mma.sync GEMM:  C[m][n] = sum_k A[m][k] * B[n][k]
// SPLIT=true: 3xTF32 split-precision (fp32-grade result) — used for QK scores.
// SPLIT=false: plain tf32, inputs rounded at fragment build — used for PV.
// ---------------------------------------------------------------------------
__device__ __forceinline__ void mma_tf32(float* d, const unsigned* a, const unsigned* b) {
    asm volatile(
        "mma.sync.aligned.m16n8k8.row.col.f32.tf32.tf32.f32 "
        "{%0,%1,%2,%3}, {%4,%5,%6,%7}, {%8,%9}, {%0,%1,%2,%3};\n"
        : "+f"(d[0]), "+f"(d[1]), "+f"(d[2]), "+f"(d[3])
        : "r"(a[0]), "r"(a[1]), "r"(a[2]), "r"(a[3]), "r"(b[0]), "r"(b[1]));
}

#define SMPAD 36

template<bool SPLIT>
__global__ void __launch_bounds__(256) gemm_tf32(
    const float* __restrict__ A, const float* __restrict__ Bm, float* __restrict__ C,
    int K,
    size_t strideA, size_t strideB, size_t strideC, int ldc)
{
    __shared__ float As[128][SMPAD];
    __shared__ float Bs[128][SMPAD];

    int b  = blockIdx.z;
    const float* Ab = A  + (size_t)b * strideA;
    const float* Bb = Bm + (size_t)b * strideB;
    float*       Cb = C  + (size_t)b * strideC;

    int bm = blockIdx.y, bn = blockIdx.x;
    int tid  = threadIdx.x;
    int warp = tid >> 5, lane = tid & 31;
    int wm = warp >> 2, wn = warp & 3;
    int g  = lane >> 2, tg = lane & 3;

    float acc[4][4][4];
    #pragma unroll
    for (int i = 0; i < 4; i++)
        #pragma unroll
        for (int j = 0; j < 4; j++)
            #pragma unroll
            for (int k = 0; k < 4; k++) acc[i][j][k] = 0.f;

    for (int kt = 0; kt < K; kt += 32) {
        __syncthreads();
        #pragma unroll
        for (int i = 0; i < 4; i++) {
            int idx = tid + i * 256;
            int row = idx >> 3;
            int c4  = (idx & 7) * 4;
            float4 av = *(const float4*)(Ab + (size_t)(bm * 128 + row) * K + kt + c4);
            float4 bv = *(const float4*)(Bb + (size_t)(bn * 128 + row) * K + kt + c4);
            *(float4*)&As[row][c4] = av;
            *(float4*)&Bs[row][c4] = bv;
        }
        __syncthreads();

        #pragma unroll
        for (int kk = 0; kk < 4; kk++) {
            if (SPLIT) {
                unsigned ah[4][4], al[4][4], bh[4][2], bl[4][2];
                #pragma unroll
                for (int mf = 0; mf < 4; mf++) {
                    int r = wm * 64 + mf * 16 + g;
                    #pragma unroll
                    for (int q = 0; q < 4; q++) {
                        float v = As[r + (q & 1) * 8][kk * 8 + tg + (q >> 1) * 4];
                        float hi = to_tf32(v);
                        ah[mf][q] = __float_as_uint(hi);
                        al[mf][q] = __float_as_uint(to_tf32(v - hi));
                    }
                }
                #pragma unroll
                for (int nf = 0; nf < 4; nf++) {
                    int c = wn * 32 + nf * 8 + g;
                    #pragma unroll
                    for (int q = 0; q < 2; q++) {
                        float v = Bs[c][kk * 8 + tg + q * 4];
                        float hi = to_tf32(v);
                        bh[nf][q] = __float_as_uint(hi);
                        bl[nf][q] = __float_as_uint(to_tf32(v - hi));
                    }
                }
                #pragma unroll
                for (int mf = 0; mf < 4; mf++)
                    #pragma unroll
                    for (int nf = 0; nf < 4; nf++) {
                        mma_tf32(acc[mf][nf], ah[mf], bl[nf]);
                        mma_tf32(acc[mf][nf], al[mf], bh[nf]);
                        mma_tf32(acc[mf][nf], ah[mf], bh[nf]);
                    }
            } else {
                unsigned afr[4][4], bfr[4][2];
                #pragma unroll
                for (int mf = 0; mf < 4; mf++) {
                    int r = wm * 64 + mf * 16 + g;
                    afr[mf][0] = __float_as_uint(to_tf32(As[r    ][kk * 8 + tg    ]));
                    afr[mf][1] = __float_as_uint(to_tf32(As[r + 8][kk * 8 + tg    ]));
                    afr[mf][2] = __float_as_uint(to_tf32(As[r    ][kk * 8 + tg + 4]));
                    afr[mf][3] = __float_as_uint(to_tf32(As[r + 8][kk * 8 + tg + 4]));
                }
                #pragma unroll
                for (int nf = 0; nf < 4; nf++) {
                    int c = wn * 32 + nf * 8 + g;
                    bfr[nf][0] = __float_as_uint(to_tf32(Bs[c][kk * 8 + tg    ]));
                    bfr[nf][1] = __float_as_uint(to_tf32(Bs[c][kk * 8 + tg + 4]));
                }
                #pragma unroll
                for (int mf = 0; mf < 4; mf++)
                    #pragma unroll
                    for (int nf = 0; nf < 4; nf++)
                        mma_tf32(acc[mf][nf], afr[mf], bfr[nf]);
            }
        }
    }

    #pragma unroll
    for (int mf = 0; mf < 4; mf++) {
        #pragma unroll
        for (int nf = 0; nf < 4; nf++) {
            int r = bm * 128 + wm * 64 + mf * 16 + g;
            int c = bn * 128 + wn * 32 + nf * 8 + tg * 2;
            *(float2*)(Cb + (size_t)r * ldc + c)       = make_float2(acc[mf][nf][0], acc[mf][nf][1]);
            *(float2*)(Cb + (size_t)(r + 8) * ldc + c) = make_float2(acc[mf][nf][2], acc[mf][nf][3]);
        }
    }
}

// ---------------------------------------------------------------------------
// Kernel 4: softmax over s (row length 2048), in place, tf32-rounded probs
// ---------------------------------------------------------------------------
__global__ void __launch_bounds__(256) softmax_kernel() {
    __shared__ float red[8];
    size_t row = blockIdx.x;
    float* p = g_S + row * (size_t)S_SRC;
    int tid  = threadIdx.x;
    int lane = tid & 31, warp = tid >> 5;

    float4 v0 = ((const float4*)p)[tid];
    float4 v1 = ((const float4*)p)[tid + 256];

    float m = fmaxf(fmaxf(fmaxf(v0.x, v0.y), fmaxf(v0.z, v0.w)),
                    fmaxf(fmaxf(v1.x, v1.y), fmaxf(v1.z, v1.w)));
    #pragma unroll
    for (int o = 16; o; o >>= 1) m = fmaxf(m, __shfl_xor_sync(0xffffffffu, m, o));
    if (lane == 0) red[warp] = m;
    __syncthreads();
    float bm = red[0];
    #pragma unroll
    for (int i = 1; i < 8; i++) bm = fmaxf(bm, red[i]);
    __syncthreads();

    v0.x = __expf(v0.x - bm); v0.y = __expf(v0.y - bm);
    v0.z = __expf(v0.z - bm); v0.w = __expf(v0.w - bm);
    v1.x = __expf(v1.x - bm); v1.y = __expf(v1.y - bm);
    v1.z = __expf(v1.z - bm); v1.w = __expf(v1.w - bm);

    float s = v0.x + v0.y + v0.z + v0.w + v1.x + v1.y + v1.z + v1.w;
    #pragma unroll
    for (int o = 16; o; o >>= 1) s += __shfl_xor_sync(0xffffffffu, s, o);
    if (lane == 0) red[warp] = s;
    __syncthreads();
    float total = red[0];
    #pragma unroll
    for (int i = 1; i < 8; i++) total += red[i];
    float inv = 1.0f / total;

    float4 o0, o1;
    o0.x = to_tf32(v0.x * inv); o0.y = to_tf32(v0.y * inv);
    o0.z = to_tf32(v0.z * inv); o0.w = to_tf32(v0.w * inv);
    o1.x = to_tf32(v1.x * inv); o1.y = to_tf32(v1.y * inv);
    o1.z = to_tf32(v1.z * inv); o1.w = to_tf32(v1.w * inv);
    ((float4*)p)[tid]       = o0;
    ((float4*)p)[tid + 256] = o1;
}

// ---------------------------------------------------------------------------
extern "C" void kernel_launch(void* const* d_in, const int* in_sizes, int n_in,
                              void* d_out, int out_size) {
    const float* out_e = (const float*)d_in[0];
    const float* out_d = (const float*)d_in[1];
    float* out = (float*)d_out;

    float *pEnc, *pEncT, *pDec, *pS;
    cudaGetSymbolAddress((void**)&pEnc,  g_enc);
    cudaGetSymbolAddress((void**)&pEncT, g_encT);
    cudaGetSymbolAddress((void**)&pDec,  g_dec);
    cudaGetSymbolAddress((void**)&pS,    g_S);

    prep_kernel<<<(BATCH * S_SRC * HDIM) / 256, 256>>>(out_e, out_d);

    transpose_kernel<<<dim3(S_SRC / 32, HDIM / 32, BATCH), dim3(32, 8)>>>();

    // S = dec . enc^T  (3xTF32 split precision: fp32-grade scores)
    gemm_tf32<true><<<dim3(S_SRC / 128, S_TGT / 128, BATCH), 256>>>(
        pDec, pEnc, pS, HDIM,
        (size_t)S_TGT * HDIM, (size_t)S_SRC * HDIM, (size_t)S_TGT * S_SRC, S_SRC);

    softmax_kernel<<<BATCH * S_TGT, 256>>>();

    // context = P . enc (plain tf32), epilogue writes [T,B,H] directly
    gemm_tf32<false><<<dim3(HDIM / 128, S_TGT / 128, BATCH), 256>>>(
        pS, pEncT, out, S_SRC,
        (size_t)S_TGT * S_SRC, (size_t)HDIM * S_SRC, (size_t)HDIM, BATCH * HDIM);
}

// round 5
// speedup vs baseline: 1.4695x; 1.4695x over previous
#include <cuda_runtime.h>
#include <cuda_bf16.h>
#include <cstdint>
#include <cstddef>

#define S_SRC 2048
#define S_TGT 2048
#define BATCH 16
#define HDIM  256

typedef __nv_bfloat16 bf16;

// ---------------------------------------------------------------------------
// Device-global scratch (allocation-free rule)
// ---------------------------------------------------------------------------
__device__ bf16  g_dec_hi [(size_t)BATCH * S_TGT * HDIM];   // [b][t][h]
__device__ bf16  g_dec_lo [(size_t)BATCH * S_TGT * HDIM];
__device__ bf16  g_enc_hi [(size_t)BATCH * S_SRC * HDIM];   // [b][s][h]
__device__ bf16  g_enc_lo [(size_t)BATCH * S_SRC * HDIM];
__device__ bf16  g_encT_hi[(size_t)BATCH * HDIM  * S_SRC];  // [b][h][s]
__device__ bf16  g_encT_lo[(size_t)BATCH * HDIM  * S_SRC];
__device__ float g_S      [(size_t)BATCH * S_TGT * S_SRC];  // fp32 scores
__device__ bf16  g_P_hi   [(size_t)BATCH * S_TGT * S_SRC];  // probs split
__device__ bf16  g_P_lo   [(size_t)BATCH * S_TGT * S_SRC];

__device__ __forceinline__ uint32_t smem_u32(const void* p) {
    uint32_t a;
    asm("{ .reg .u64 t; cvta.to.shared.u64 t, %1; cvt.u32.u64 %0, t; }" : "=r"(a) : "l"(p));
    return a;
}

__device__ __forceinline__ void cp_async16(uint32_t dst, const void* src) {
    asm volatile("cp.async.cg.shared.global [%0], [%1], 16;" :: "r"(dst), "l"(src));
}
#define CP_COMMIT() asm volatile("cp.async.commit_group;")
#define CP_WAIT(N)  asm volatile("cp.async.wait_group %0;" :: "n"(N))

__device__ __forceinline__ void ldsm4(unsigned* r, uint32_t a) {
    asm volatile("ldmatrix.sync.aligned.m8n8.x4.shared.b16 {%0,%1,%2,%3}, [%4];"
                 : "=r"(r[0]), "=r"(r[1]), "=r"(r[2]), "=r"(r[3]) : "r"(a));
}

__device__ __forceinline__ void mma_bf16(float* d, const unsigned* a, const unsigned* b) {
    asm volatile(
        "mma.sync.aligned.m16n8k16.row.col.f32.bf16.bf16.f32 "
        "{%0,%1,%2,%3}, {%4,%5,%6,%7}, {%8,%9}, {%0,%1,%2,%3};\n"
        : "+f"(d[0]), "+f"(d[1]), "+f"(d[2]), "+f"(d[3])
        : "r"(a[0]), "r"(a[1]), "r"(a[2]), "r"(a[3]), "r"(b[0]), "r"(b[1]));
}

__device__ __forceinline__ void split_bf16(float v, bf16& hi, bf16& lo) {
    hi = __float2bfloat16(v);
    lo = __float2bfloat16(v - __bfloat162float(hi));
}

// ---------------------------------------------------------------------------
// Kernel 1: prep — enc = dir0+dir1 (split), dec (split), batch-major [b][r][h]
// ---------------------------------------------------------------------------
__global__ void __launch_bounds__(256) prep_kernel(const float* __restrict__ out_e,
                                                   const float* __restrict__ out_d) {
    int i = blockIdx.x * blockDim.x + threadIdx.x;
    int h = i & (HDIM - 1);
    int s = (i >> 8) & (S_SRC - 1);
    int b = i >> 19;
    size_t ebase = ((size_t)s * BATCH + b) * (2 * HDIM);
    float e = out_e[ebase + h] + out_e[ebase + HDIM + h];
    size_t idx = ((size_t)b * S_SRC + s) * HDIM + h;
    bf16 hi, lo;
    split_bf16(e, hi, lo);
    g_enc_hi[idx] = hi; g_enc_lo[idx] = lo;
    float d = out_d[((size_t)s * BATCH + b) * HDIM + h];
    split_bf16(d, hi, lo);
    g_dec_hi[idx] = hi; g_dec_lo[idx] = lo;
}

// ---------------------------------------------------------------------------
// Kernel 2: encT split — reads out_e directly, writes [b][h][s] bf16 hi/lo
// ---------------------------------------------------------------------------
__global__ void __launch_bounds__(256) transposeE_kernel(const float* __restrict__ out_e) {
    __shared__ uint32_t tile[32][33];   // packed (lo<<16)|hi
    int b  = blockIdx.z;
    int s0 = blockIdx.x * 32;
    int h0 = blockIdx.y * 32;
    int x = threadIdx.x;
    #pragma unroll
    for (int y = threadIdx.y; y < 32; y += 8) {
        size_t ebase = ((size_t)(s0 + y) * BATCH + b) * (2 * HDIM) + h0 + x;
        float e = out_e[ebase] + out_e[ebase + HDIM];
        bf16 hi, lo;
        split_bf16(e, hi, lo);
        tile[y][x] = ((uint32_t)__bfloat16_as_ushort(lo) << 16) | __bfloat16_as_ushort(hi);
    }
    __syncthreads();
    #pragma unroll
    for (int y = threadIdx.y; y < 32; y += 8) {
        uint32_t v = tile[x][y];
        size_t o = ((size_t)b * HDIM + h0 + y) * S_SRC + s0 + x;
        g_encT_hi[o] = __ushort_as_bfloat16((unsigned short)(v & 0xFFFF));
        g_encT_lo[o] = __ushort_as_bfloat16((unsigned short)(v >> 16));
    }
}

// ---------------------------------------------------------------------------
// Split-bf16 GEMM:  C[m][n] = sum_k A[m][k]*B[n][k], A=Ah+Al, B=Bh+Bl,
// products hh + hl + lh. Block 128x128, K-chunk 32, double-buffered cp.async.
// 8 warps (2m x 4n), warp tile 64x32. ldmatrix.x4 fragments, 80B row stride.
// ---------------------------------------------------------------------------
#define ROWB   80                      // 32 bf16 padded to 40 (80 B) -> conflict-free
#define ARR    (128 * ROWB)            // 10240 B per operand array
#define STG    (4 * ARR)               // 40960 B per stage
#define GSMEM  (2 * STG)

__device__ __forceinline__ void load_tile(uint32_t dst, const bf16* __restrict__ g, int ldg) {
    #pragma unroll
    for (int it = threadIdx.x; it < 512; it += 256) {
        int row = it >> 2, seg = it & 3;
        cp_async16(dst + row * ROWB + seg * 16, g + (size_t)row * ldg + seg * 8);
    }
}

__global__ void __launch_bounds__(256) gemm_split(
    const bf16* __restrict__ Ah, const bf16* __restrict__ Al,
    const bf16* __restrict__ Bh, const bf16* __restrict__ Bl,
    float* __restrict__ C, int K,
    size_t strideA, size_t strideB, size_t strideC, int lda, int ldb, int ldc)
{
    extern __shared__ char smem[];
    uint32_t sbase = smem_u32(smem);

    int b  = blockIdx.z;
    int bm = blockIdx.y, bn = blockIdx.x;
    const bf16* Ahp = Ah + (size_t)b * strideA + (size_t)(bm * 128) * lda;
    const bf16* Alp = Al + (size_t)b * strideA + (size_t)(bm * 128) * lda;
    const bf16* Bhp = Bh + (size_t)b * strideB + (size_t)(bn * 128) * ldb;
    const bf16* Blp = Bl + (size_t)b * strideB + (size_t)(bn * 128) * ldb;
    float*      Cb  = C  + (size_t)b * strideC;

    int tid  = threadIdx.x;
    int warp = tid >> 5, lane = tid & 31;
    int wm = warp >> 2, wn = warp & 3;
    int g  = lane >> 2, tg = lane & 3;

    // ldmatrix lane addressing
    int rA = (lane & 7) + ((lane >> 3) & 1) * 8;
    int cA = (lane >> 4) & 1;
    int rB = (lane & 7) + ((lane >> 4) & 1) * 8;
    int cB = (lane >> 3) & 1;
    uint32_t aOffH = 0 * ARR + (uint32_t)(wm * 64 + rA) * ROWB + cA * 16;
    uint32_t aOffL = 1 * ARR + (uint32_t)(wm * 64 + rA) * ROWB + cA * 16;
    uint32_t bOffH = 2 * ARR + (uint32_t)(wn * 32 + rB) * ROWB + cB * 16;
    uint32_t bOffL = 3 * ARR + (uint32_t)(wn * 32 + rB) * ROWB + cB * 16;

    float acc[4][4][4];
    #pragma unroll
    for (int i = 0; i < 4; i++)
        #pragma unroll
        for (int j = 0; j < 4; j++)
            #pragma unroll
            for (int k = 0; k < 4; k++) acc[i][j][k] = 0.f;

    int NCH = K >> 5;

    // prefetch chunk 0 -> stage 0
    load_tile(sbase + 0 * ARR, Ahp, lda);
    load_tile(sbase + 1 * ARR, Alp, lda);
    load_tile(sbase + 2 * ARR, Bhp, ldb);
    load_tile(sbase + 3 * ARR, Blp, ldb);
    CP_COMMIT();

    for (int c = 0; c < NCH; c++) {
        if (c + 1 < NCH) {
            uint32_t st = sbase + ((c + 1) & 1) * STG;
            int k0 = (c + 1) * 32;
            load_tile(st + 0 * ARR, Ahp + k0, lda);
            load_tile(st + 1 * ARR, Alp + k0, lda);
            load_tile(st + 2 * ARR, Bhp + k0, ldb);
            load_tile(st + 3 * ARR, Blp + k0, ldb);
            CP_COMMIT();
            CP_WAIT(1);
        } else {
            CP_WAIT(0);
        }
        __syncthreads();

        uint32_t sb = sbase + (c & 1) * STG;
        #pragma unroll
        for (int step = 0; step < 2; step++) {
            unsigned ah[4][4], al[4][4];
            #pragma unroll
            for (int mf = 0; mf < 4; mf++) {
                ldsm4(ah[mf], sb + aOffH + mf * 16 * ROWB + step * 32);
                ldsm4(al[mf], sb + aOffL + mf * 16 * ROWB + step * 32);
            }
            unsigned bh[2][4];
            ldsm4(bh[0], sb + bOffH + step * 32);
            ldsm4(bh[1], sb + bOffH + 16 * ROWB + step * 32);
            #pragma unroll
            for (int mf = 0; mf < 4; mf++)
                #pragma unroll
                for (int nf = 0; nf < 4; nf++) {
                    unsigned bfr[2] = { bh[nf >> 1][(nf & 1) * 2],
                                        bh[nf >> 1][(nf & 1) * 2 + 1] };
                    mma_bf16(acc[mf][nf], ah[mf], bfr);   // hh
                    mma_bf16(acc[mf][nf], al[mf], bfr);   // lh
                }
            unsigned bl[2][4];
            ldsm4(bl[0], sb + bOffL + step * 32);
            ldsm4(bl[1], sb + bOffL + 16 * ROWB + step * 32);
            #pragma unroll
            for (int mf = 0; mf < 4; mf++)
                #pragma unroll
                for (int nf = 0; nf < 4; nf++) {
                    unsigned bfr[2] = { bl[nf >> 1][(nf & 1) * 2],
                                        bl[nf >> 1][(nf & 1) * 2 + 1] };
                    mma_bf16(acc[mf][nf], ah[mf], bfr);   // hl
                }
        }
        __syncthreads();
    }

    #pragma unroll
    for (int mf = 0; mf < 4; mf++) {
        #pragma unroll
        for (int nf = 0; nf < 4; nf++) {
            int r = bm * 128 + wm * 64 + mf * 16 + g;
            int c = bn * 128 + wn * 32 + nf * 8 + tg * 2;
            *(float2*)(Cb + (size_t)r * ldc + c)       = make_float2(acc[mf][nf][0], acc[mf][nf][1]);
            *(float2*)(Cb + (size_t)(r + 8) * ldc + c) = make_float2(acc[mf][nf][2], acc[mf][nf][3]);
        }
    }
}

// ---------------------------------------------------------------------------
// Kernel 4: softmax over s, reads fp32 S, writes split-bf16 P
// ---------------------------------------------------------------------------
__global__ void __launch_bounds__(256) softmax_kernel() {
    __shared__ float red[8];
    size_t row = blockIdx.x;
    const float* p = g_S + row * (size_t)S_SRC;
    int tid  = threadIdx.x;
    int lane = tid & 31, warp = tid >> 5;

    float4 v0 = ((const float4*)p)[tid];
    float4 v1 = ((const float4*)p)[tid + 256];

    float m = fmaxf(fmaxf(fmaxf(v0.x, v0.y), fmaxf(v0.z, v0.w)),
                    fmaxf(fmaxf(v1.x, v1.y), fmaxf(v1.z, v1.w)));
    #pragma unroll
    for (int o = 16; o; o >>= 1) m = fmaxf(m, __shfl_xor_sync(0xffffffffu, m, o));
    if (lane == 0) red[warp] = m;
    __syncthreads();
    float bm = red[0];
    #pragma unroll
    for (int i = 1; i < 8; i++) bm = fmaxf(bm, red[i]);
    __syncthreads();

    v0.x = __expf(v0.x - bm); v0.y = __expf(v0.y - bm);
    v0.z = __expf(v0.z - bm); v0.w = __expf(v0.w - bm);
    v1.x = __expf(v1.x - bm); v1.y = __expf(v1.y - bm);
    v1.z = __expf(v1.z - bm); v1.w = __expf(v1.w - bm);

    float s = v0.x + v0.y + v0.z + v0.w + v1.x + v1.y + v1.z + v1.w;
    #pragma unroll
    for (int o = 16; o; o >>= 1) s += __shfl_xor_sync(0xffffffffu, s, o);
    if (lane == 0) red[warp] = s;
    __syncthreads();
    float total = red[0];
    #pragma unroll
    for (int i = 1; i < 8; i++) total += red[i];
    float inv = 1.0f / total;

    bf16* ph = g_P_hi + row * (size_t)S_SRC;
    bf16* pl = g_P_lo + row * (size_t)S_SRC;
    float vv[8] = { v0.x, v0.y, v0.z, v0.w, v1.x, v1.y, v1.z, v1.w };
    bf16 hb[8], lb[8];
    #pragma unroll
    for (int q = 0; q < 8; q++) {
        float pv = vv[q] * inv;
        split_bf16(pv, hb[q], lb[q]);
    }
    // elements q 0-3 at tid*4, q 4-7 at (256+tid)*4
    *(uint2*)(ph + (size_t)tid * 4)         = *(uint2*)&hb[0];
    *(uint2*)(ph + (size_t)(256 + tid) * 4) = *(uint2*)&hb[4];
    *(uint2*)(pl + (size_t)tid * 4)         = *(uint2*)&lb[0];
    *(uint2*)(pl + (size_t)(256 + tid) * 4) = *(uint2*)&lb[4];
}

// ---------------------------------------------------------------------------
extern "C" void kernel_launch(void* const* d_in, const int* in_sizes, int n_in,
                              void* d_out, int out_size) {
    const float* out_e = (const float*)d_in[0];
    const float* out_d = (const float*)d_in[1];
    float* out = (float*)d_out;

    bf16 *pDh, *pDl, *pEh, *pEl, *pTh, *pTl, *pPh, *pPl;
    float* pS;
    cudaGetSymbolAddress((void**)&pDh, g_dec_hi);
    cudaGetSymbolAddress((void**)&pDl, g_dec_lo);
    cudaGetSymbolAddress((void**)&pEh, g_enc_hi);
    cudaGetSymbolAddress((void**)&pEl, g_enc_lo);
    cudaGetSymbolAddress((void**)&pTh, g_encT_hi);
    cudaGetSymbolAddress((void**)&pTl, g_encT_lo);
    cudaGetSymbolAddress((void**)&pPh, g_P_hi);
    cudaGetSymbolAddress((void**)&pPl, g_P_lo);
    cudaGetSymbolAddress((void**)&pS,  g_S);

    cudaFuncSetAttribute(gemm_split, cudaFuncAttributeMaxDynamicSharedMemorySize, GSMEM);

    prep_kernel<<<(BATCH * S_SRC * HDIM) / 256, 256>>>(out_e, out_d);

    transposeE_kernel<<<dim3(S_SRC / 32, HDIM / 32, BATCH), dim3(32, 8)>>>(out_e);

    // QK: S[b][t][s] = dec . enc  (M=2048, N=2048, K=256)
    gemm_split<<<dim3(S_SRC / 128, S_TGT / 128, BATCH), 256, GSMEM>>>(
        pDh, pDl, pEh, pEl, pS, HDIM,
        (size_t)S_TGT * HDIM, (size_t)S_SRC * HDIM, (size_t)S_TGT * S_SRC,
        HDIM, HDIM, S_SRC);

    softmax_kernel<<<BATCH * S_TGT, 256>>>();

    // PV: out[t][b][h] = P . encT  (M=2048, N=256, K=2048)
    gemm_split<<<dim3(HDIM / 128, S_TGT / 128, BATCH), 256, GSMEM>>>(
        pPh, pPl, pTh, pTl, out + 0, S_SRC,
        (size_t)S_TGT * S_SRC, (size_t)HDIM * S_SRC, (size_t)HDIM,
        S_SRC, S_SRC, BATCH * HDIM);
}